// round 17
// baseline (speedup 1.0000x reference)
#include <cuda_runtime.h>
#include <cstdint>

#define VOCAB 50000
#define EDIM  256
#define HDIM  256
#define BATCH 64
#define TLEN  2048

#define CANARY 0x7FC00BADu

typedef unsigned long long u64;

// proj_table[v][h] = sum_e emb[v][e] * W_ih[h][e]   (51.2 MB device scratch)
__device__ float g_proj[VOCAB * HDIM];

// ---------------------------------------------------------------------------
// Kernel A: proj = emb @ W_ih^T   (NT SGEMM, C[50000,256])  -- unchanged
// ---------------------------------------------------------------------------
__global__ __launch_bounds__(256) void proj_kernel(const float* __restrict__ emb,
                                                   const float* __restrict__ Wih) {
    __shared__ float As[32][128];
    __shared__ float Bs[32][128];

    const int n0 = blockIdx.x * 128;
    const int m0 = blockIdx.y * 128;
    const int tid = threadIdx.x;
    const int tx = tid & 15;
    const int ty = tid >> 4;

    float acc[8][8];
#pragma unroll
    for (int a = 0; a < 8; a++)
#pragma unroll
        for (int bb = 0; bb < 8; bb++) acc[a][bb] = 0.0f;

    for (int kc = 0; kc < EDIM; kc += 32) {
#pragma unroll
        for (int q = 0; q < 4; q++) {
            int fid = tid + 256 * q;
            int row = fid >> 3;
            int col = fid & 7;
            float4 av = make_float4(0.f, 0.f, 0.f, 0.f);
            int m = m0 + row;
            if (m < VOCAB)
                av = __ldg((const float4*)(emb + (size_t)m * EDIM + kc + col * 4));
            As[col * 4 + 0][row] = av.x;
            As[col * 4 + 1][row] = av.y;
            As[col * 4 + 2][row] = av.z;
            As[col * 4 + 3][row] = av.w;
            float4 bv = __ldg((const float4*)(Wih + (size_t)(n0 + row) * EDIM + kc + col * 4));
            Bs[col * 4 + 0][row] = bv.x;
            Bs[col * 4 + 1][row] = bv.y;
            Bs[col * 4 + 2][row] = bv.z;
            Bs[col * 4 + 3][row] = bv.w;
        }
        __syncthreads();

#pragma unroll
        for (int k = 0; k < 32; k++) {
            float a[8], b[8];
            *(float4*)&a[0] = *(const float4*)&As[k][ty * 8];
            *(float4*)&a[4] = *(const float4*)&As[k][ty * 8 + 4];
            *(float4*)&b[0] = *(const float4*)&Bs[k][tx * 8];
            *(float4*)&b[4] = *(const float4*)&Bs[k][tx * 8 + 4];
#pragma unroll
            for (int ii = 0; ii < 8; ii++)
#pragma unroll
                for (int jj = 0; jj < 8; jj++) acc[ii][jj] += a[ii] * b[jj];
        }
        __syncthreads();
    }

#pragma unroll
    for (int ii = 0; ii < 8; ii++) {
        int m = m0 + ty * 8 + ii;
        if (m < VOCAB) {
            float4 v0 = make_float4(acc[ii][0], acc[ii][1], acc[ii][2], acc[ii][3]);
            float4 v1 = make_float4(acc[ii][4], acc[ii][5], acc[ii][6], acc[ii][7]);
            *(float4*)(g_proj + (size_t)m * HDIM + n0 + tx * 8)     = v0;
            *(float4*)(g_proj + (size_t)m * HDIM + n0 + tx * 8 + 4) = v1;
        }
    }
}

// ---------------------------------------------------------------------------
// Kernel B: RNN scan, PARTIAL-SUM exchange. 64 clusters x 2 CTAs x 1024 thr.
// Each CTA keeps only its OWN h half (hloc). Per step, every thread group
// (4 lanes per output o, K-slice s within the LOCAL 128 K's) computes
// P[o] = sum_k W[o][ownK+k] * hloc[k]  for ALL 256 outputs (local data only).
// Groups whose o is in the PEER half send P[o] (one scalar DSMEM store);
// groups whose o is ours poll recv[par][o&127] (the polled word IS the
// operand), then h_new = tanh(xp + P + R). One __syncthreads per step, no
// named barriers. t=0: P=R=0 (h0=0) -> skip send/poll. recv slots parity-
// unique, poisoned post-read (peer's next write causally follows our next
// send, which follows this step's __syncthreads).
// ---------------------------------------------------------------------------
__device__ __forceinline__ void fma2(u64& acc, u64 a, u64 b) {
    asm("fma.rn.f32x2 %0, %1, %2, %0;" : "+l"(acc) : "l"(a), "l"(b));
}
__device__ __forceinline__ uint32_t s2u(const void* p) {
    return (uint32_t)__cvta_generic_to_shared(p);
}
__device__ __forceinline__ uint32_t mapa_u32(uint32_t a, uint32_t r) {
    uint32_t ret;
    asm("mapa.shared::cluster.u32 %0, %1, %2;" : "=r"(ret) : "r"(a), "r"(r));
    return ret;
}
__device__ __forceinline__ void st_remote_f32(uint32_t ra, float v) {
    asm volatile("st.shared::cluster.f32 [%0], %1;" :: "r"(ra), "f"(v) : "memory");
}
__device__ __forceinline__ uint32_t lds_vol_u32(uint32_t a) {
    uint32_t v;
    asm volatile("ld.volatile.shared.u32 %0, [%1];" : "=r"(v) : "r"(a) : "memory");
    return v;
}
__device__ __forceinline__ void cl_arrive() {
    asm volatile("barrier.cluster.arrive.aligned;" ::: "memory");
}
__device__ __forceinline__ void cl_wait() {
    asm volatile("barrier.cluster.wait.aligned;" ::: "memory");
}
// exact-enough tanh (validated rel_err ~2.8e-7 end-to-end, R5-R15)
__device__ __forceinline__ float fast_tanh(float x) {
    float xc = fminf(fmaxf(x, -15.0f), 15.0f);
    float e  = __expf(2.0f * xc);
    return __fdividef(e - 1.0f, e + 1.0f);
}

__global__ void __cluster_dims__(2, 1, 1) __launch_bounds__(1024, 1)
scan_kernel(const int* __restrict__ reviews, const int* __restrict__ lengths,
            const float* __restrict__ Whh, const float* __restrict__ Wcls,
            const float* __restrict__ bcls, float* __restrict__ out) {
    __shared__ __align__(16) float hloc[2][128];    // OWN h half, double-buffered
    __shared__ __align__(16) float recvb[2][128];   // incoming peer partials
    __shared__ float hfin[256];                     // final h staging (rank 0)
    __shared__ int toks[TLEN];

    const int tid  = threadIdx.x;
    const int o    = tid >> 2;              // global output index 0..255
    const int s    = tid & 3;               // K-slice within LOCAL 128 K's
    const int b    = blockIdx.x >> 1;
    const int rank = blockIdx.x & 1;
    const int peer = rank ^ 1;
    const int len  = lengths[b];
    const int ownK = rank * 128;
    const bool mine = ((o >> 7) == rank);   // is output o in my half?
    const int oloc = o & 127;

    for (int idx = tid; idx < TLEN; idx += 1024)
        toks[idx] = reviews[b * TLEN + idx];
    if (tid < 128) hloc[0][tid] = 0.0f;                 // h(0) = 0
    if (tid < 256) ((uint32_t*)recvb)[tid] = CANARY;    // both parities armed

    // W_hh[o][ownK + s*32 .. +31] as 16 packed f32x2 (row o, my K columns)
    u64 w[16];
    {
        const u64* wp = (const u64*)(Whh + (size_t)o * HDIM + ownK + s * 32);
#pragma unroll
        for (int q = 0; q < 16; q++) w[q] = wp[q];
    }
    __syncthreads();
    cl_arrive(); cl_wait();                 // peer's canary init visible

    // sender remote slots (lane s==0 of peer-output groups), both parities
    uint32_t rR0 = 0, rR1 = 0;
    if (!mine && s == 0) {
        rR0 = mapa_u32(s2u(&recvb[0][oloc]), peer);
        rR1 = mapa_u32(s2u(&recvb[1][oloc]), peer);
    }
    // finisher poll addresses (all 4 lanes, broadcast)
    const uint32_t pr0 = s2u(&recvb[0][oloc]);
    const uint32_t pr1 = s2u(&recvb[1][oloc]);

    float xp_cur = 0.0f;
    if (mine) xp_cur = __ldg(g_proj + (size_t)toks[0] * HDIM + o);

    for (int t = 0; t < len; ++t) {
        const int p = t & 1, pn = p ^ 1;

        float xp_next = 0.0f;
        if (mine) {
            int tn = (t + 1 < len) ? (t + 1) : t;
            xp_next = __ldg(g_proj + (size_t)toks[tn] * HDIM + o);
        }

        // partial P[o] over my local K's (local data only)
        u64 a0 = 0ull, a1 = 0ull, a2 = 0ull, a3 = 0ull;
        const ulonglong2* hp = (const ulonglong2*)&hloc[p][s * 32];
#pragma unroll
        for (int q = 0; q < 4; q++) {
            ulonglong2 h0 = hp[2 * q];
            ulonglong2 h1 = hp[2 * q + 1];
            fma2(a0, w[4 * q],     h0.x);
            fma2(a1, w[4 * q + 1], h0.y);
            fma2(a2, w[4 * q + 2], h1.x);
            fma2(a3, w[4 * q + 3], h1.y);
        }
        float2 f0 = *(float2*)&a0, f1 = *(float2*)&a1;
        float2 f2 = *(float2*)&a2, f3 = *(float2*)&a3;
        float P = (f0.x + f0.y) + (f1.x + f1.y) + (f2.x + f2.y) + (f3.x + f3.y);
        P += __shfl_xor_sync(0xffffffffu, P, 1);
        P += __shfl_xor_sync(0xffffffffu, P, 2);    // all 4 lanes hold P[o]

        if (!mine) {
            // sender: ship P[o] to the peer's recv slot (skip t=0: P==0 known)
            if (t > 0 && s == 0) st_remote_f32(p ? rR1 : rR0, P);
        } else {
            // finisher: R from peer (0 at t=0), then tanh + store
            float R = 0.0f;
            if (t > 0) {
                const uint32_t pa = p ? pr1 : pr0;
                uint32_t u;
                for (;;) {
                    u = lds_vol_u32(pa);
                    if (__all_sync(0xffffffffu, u != CANARY)) break;
                }
                R = __uint_as_float(u);
                if (s == 1) *(uint32_t*)&recvb[p][oloc] = CANARY;  // re-arm
            }
            float v = fast_tanh(xp_cur + P + R);
            if (s == 0) hloc[pn][oloc] = v;
            xp_cur = xp_next;
        }
        __syncthreads();                    // h(t+1) local half visible
    }

    // stage final h into rank 0's hfin
    if (tid < 128) {
        float hv = hloc[len & 1][tid];
        if (rank == 0) hfin[tid] = hv;
        else st_remote_f32(mapa_u32(s2u(&hfin[128 + tid]), 0), hv);
    }
    cl_arrive(); cl_wait();                 // DSMEM stores ordered + visible

    if (rank == 0 && tid < 64) {
        int c = tid >> 5, ln = tid & 31;
        float sum = 0.0f;
#pragma unroll
        for (int m = 0; m < 8; m++)
            sum += Wcls[c * HDIM + ln + 32 * m] * hfin[ln + 32 * m];
#pragma unroll
        for (int oo = 16; oo > 0; oo >>= 1)
            sum += __shfl_down_sync(0xffffffffu, sum, oo);
        if (ln == 0) out[b * 2 + c] = sum + bcls[c];
    }

    // keep both CTAs alive until all cross-CTA traffic has landed
    cl_arrive(); cl_wait();
}

// ---------------------------------------------------------------------------
extern "C" void kernel_launch(void* const* d_in, const int* in_sizes, int n_in,
                              void* d_out, int out_size) {
    const int*   reviews = (const int*)d_in[0];
    const int*   lengths = (const int*)d_in[1];
    const float* emb     = (const float*)d_in[2];
    const float* Wih     = (const float*)d_in[3];
    const float* Whh     = (const float*)d_in[4];
    const float* Wcls    = (const float*)d_in[5];
    const float* bcls    = (const float*)d_in[6];
    float*       out     = (float*)d_out;

    dim3 gA(2, (VOCAB + 127) / 128);
    proj_kernel<<<gA, 256>>>(emb, Wih);

    scan_kernel<<<BATCH * 2, 1024>>>(reviews, lengths, Whh, Wcls, bcls, out);
}